// round 12
// baseline (speedup 1.0000x reference)
#include <cuda_runtime.h>
#include <math.h>

#define NROWS     32768
#define CDIM      256
#define KCODES    1024
#define BLK_M     128
#define SPB       4096          // spatial positions per batch element (16*16*16)
#define ZQ_ELEMS  8388608       // 8*256*4096
#define EPAD      132           // padded row stride for E-tile in smem
#define EBUF_OFF  32768         // Zs = 256*128 floats
// Zs + Ebuf(32*132) + sIdx + aRow + b2s + red
#define SMEM_FLOATS (32768 + 4224 + 128 + 128 + 1024 + 8)

__device__ float g_b2[KCODES];      // sum e_k^2, strict sequential rounding
__device__ int   g_counts[KCODES];
__device__ float g_sse;
__device__ int   g_done;

// ---- packed fp32x2 helpers (Blackwell dual-rate fp32 pipe) --------------
__device__ __forceinline__ unsigned long long pk2(float x) {
    unsigned long long r;
    asm("mov.b64 %0, {%1, %1};" : "=l"(r) : "f"(x));
    return r;
}
__device__ __forceinline__ void fma2(unsigned long long& d,
                                     unsigned long long a, unsigned long long b) {
    asm("fma.rn.f32x2 %0, %1, %2, %0;" : "+l"(d) : "l"(a), "l"(b));
}
__device__ __forceinline__ void upk(unsigned long long v, float& lo, float& hi) {
    asm("mov.b64 {%0, %1}, %2;" : "=f"(lo), "=f"(hi) : "l"(v));
}

// ---------------------------------------------------------------------------
// Kernel 1: b_k = sum_c fl(fl(e^2)+...) sequential ascending c (strict, no fma)
// 64 blocks x 256 threads, 16 codes per block.
// ---------------------------------------------------------------------------
__global__ void bias_kernel(const float* __restrict__ emb) {
    __shared__ float sb[16 * 257];
    const int tid = threadIdx.x;
    const int k0 = blockIdx.x * 16;
    const float4* src = (const float4*)(emb + (size_t)k0 * CDIM);
    for (int i = tid; i < 1024; i += 256) {       // 16 rows x 64 float4
        float4 v = src[i];
        int r = i >> 6, c = (i & 63) * 4;
        float* d = &sb[r * 257 + c];
        d[0]=v.x; d[1]=v.y; d[2]=v.z; d[3]=v.w;
    }
    __syncthreads();
    if (tid < 16) {
        const float* e = &sb[tid * 257];
        float s = 0.f;
        for (int c = 0; c < CDIM; c++)
            s = __fadd_rn(s, __fmul_rn(e[c], e[c]));
        g_b2[k0 + tid] = s;
        g_counts[k0 + tid] = 0;
    }
    if (blockIdx.x == 0 && tid == 16) g_sse = 0.f;
}

// ---------------------------------------------------------------------------
// Kernel 2: main — distance GEMM (FFMA2) + argmin + gather z_q + SSE + counts
//           + fused finalize in the last-finishing block
// (mainloop structure identical to the 397us R4 kernel)
// ---------------------------------------------------------------------------
__global__ __launch_bounds__(256, 1)
void vq_main_kernel(const float* __restrict__ z, const float* __restrict__ emb,
                    float* __restrict__ out, int writeIdx, int writeScalars) {
    extern __shared__ float sm[];
    float* Zs   = sm;                             // [256 c][128 m]
    float* Ebuf = sm + EBUF_OFF;                  // [32 cc][132]
    int*   sIdx = (int*)(sm + EBUF_OFF + 4224);
    float* aRow = sm + EBUF_OFF + 4224 + 128;
    float* b2s  = sm + EBUF_OFF + 4224 + 256;
    float* red  = sm + EBUF_OFF + 4224 + 256 + 1024;

    const int tid = threadIdx.x;
    const int tx = tid & 15, ty = tid >> 4;
    const int n0 = blockIdx.x * BLK_M;
    const int b  = n0 >> 12;
    const int s0 = n0 & (SPB - 1);
    const float* zb = z + (size_t)b * (CDIM * SPB) + s0;

    // ---- stage b2 into smem (coalesced) ----
    for (int i = tid; i < KCODES; i += 256) b2s[i] = g_b2[i];

    // ---- load Z tile into smem (transposed to [c][m]), coalesced ----
    {
        int lane4 = (tid & 31) * 4;
        for (int c = tid >> 5; c < CDIM; c += 8) {
            float4 v = *(const float4*)(zb + (size_t)c * SPB + lane4);
            *(float4*)&Zs[c * BLK_M + lane4] = v;
        }
    }
    __syncthreads();

    // ---- a_m = sum_c fl(fl(z^2)+...) sequential ascending c (strict) ----
    if (tid < BLK_M) {
        float s = 0.f;
        for (int c = 0; c < CDIM; c++) {
            float v = Zs[c * BLK_M + tid];
            s = __fadd_rn(s, __fmul_rn(v, v));
        }
        aRow[tid] = s;
    }
    __syncthreads();

    float av[8];
#pragma unroll
    for (int i = 0; i < 8; i++) {
        int m = (i < 4) ? (ty * 4 + i) : (64 + ty * 4 + i - 4);
        av[i] = aRow[m];
    }

    float bestv[8];
    int   bestk[8];
#pragma unroll
    for (int i = 0; i < 8; i++) { bestv[i] = 3.4e38f; bestk[i] = 0; }

    const int cc0 = tid & 31, kk0 = tid >> 5;
    float er[16];
    {   // prefetch E chunk (ktile 0, cchunk 0)
        const float* ep = emb + (size_t)kk0 * CDIM + cc0;
#pragma unroll
        for (int i = 0; i < 16; i++) er[i] = ep[(size_t)(8 * i) * CDIM];
    }

    for (int kt = 0; kt < 8; kt++) {
        unsigned long long acc2[4][8];   // (row pair) x (8 k-cols), packed fp32x2
#pragma unroll
        for (int p = 0; p < 4; p++)
#pragma unroll
            for (int j = 0; j < 8; j++) acc2[p][j] = 0ull;

        for (int ch = 0; ch < 8; ch++) {
            __syncthreads();
#pragma unroll
            for (int i = 0; i < 16; i++) Ebuf[cc0 * EPAD + kk0 + 8 * i] = er[i];
            __syncthreads();
            int nch = ch + 1, nkt = kt;
            if (nch == 8) { nch = 0; nkt++; }
            if (nkt < 8) {
                const float* ep = emb + (size_t)(nkt * 128 + kk0) * CDIM + nch * 32 + cc0;
#pragma unroll
                for (int i = 0; i < 16; i++) er[i] = ep[(size_t)(8 * i) * CDIM];
            }
            const int cbase = ch * 32;
#pragma unroll
            for (int cc = 0; cc < 32; cc++) {
                const float* zrow = &Zs[(cbase + cc) * BLK_M];
                ulonglong2 z0 = *(const ulonglong2*)(zrow + ty * 4);        // rows i0..i3
                ulonglong2 z1 = *(const ulonglong2*)(zrow + 64 + ty * 4);   // rows i4..i7
                float4 e0 = *(const float4*)&Ebuf[cc * EPAD + tx * 4];
                float4 e1 = *(const float4*)&Ebuf[cc * EPAD + 64 + tx * 4];
                unsigned long long eb2[8] = {
                    pk2(e0.x), pk2(e0.y), pk2(e0.z), pk2(e0.w),
                    pk2(e1.x), pk2(e1.y), pk2(e1.z), pk2(e1.w)};
#pragma unroll
                for (int j = 0; j < 8; j++) {
                    fma2(acc2[0][j], z0.x, eb2[j]);
                    fma2(acc2[1][j], z0.y, eb2[j]);
                    fma2(acc2[2][j], z1.x, eb2[j]);
                    fma2(acc2[3][j], z1.y, eb2[j]);
                }
            }
        }
        // ---- unpack + fold: d = fl(fl(a+b_k) - fl(2*dot)), argmin ----
        const int k0 = kt * 128;
        float bj[8];
#pragma unroll
        for (int j = 0; j < 8; j++) {
            int kl = (j < 4) ? (tx * 4 + j) : (64 + tx * 4 + j - 4);
            bj[j] = b2s[k0 + kl];
        }
#pragma unroll
        for (int p = 0; p < 4; p++) {
#pragma unroll
            for (int j = 0; j < 8; j++) {
                float dlo, dhi;
                upk(acc2[p][j], dlo, dhi);
                int i0 = 2 * p, i1 = 2 * p + 1;
                int kl = (j < 4) ? (tx * 4 + j) : (64 + tx * 4 + j - 4);
                float t0 = __fadd_rn(av[i0], bj[j]);
                float d0 = __fsub_rn(t0, __fadd_rn(dlo, dlo));
                if (d0 < bestv[i0]) { bestv[i0] = d0; bestk[i0] = k0 + kl; }
                float t1 = __fadd_rn(av[i1], bj[j]);
                float d1 = __fsub_rn(t1, __fadd_rn(dhi, dhi));
                if (d1 < bestv[i1]) { bestv[i1] = d1; bestk[i1] = k0 + kl; }
            }
        }
    }

    // ---- reduce argmin across the 16 tx threads of each row ----
    float* rv = Ebuf;
    int*   rk = (int*)(Ebuf + 2048);
    __syncthreads();
#pragma unroll
    for (int i = 0; i < 8; i++) {
        int m = (i < 4) ? (ty * 4 + i) : (64 + ty * 4 + i - 4);
        rv[m * 16 + tx] = bestv[i];
        rk[m * 16 + tx] = bestk[i];
    }
    __syncthreads();
    if (tid < BLK_M) {
        int m = tid;
        float bv = 3.4e38f; int bk = KCODES;
        for (int i = 0; i < 16; i++) {
            float v = rv[m * 16 + i]; int k = rk[m * 16 + i];
            if (v < bv || (v == bv && k < bk)) { bv = v; bk = k; }
        }
        sIdx[m] = bk;
        atomicAdd(&g_counts[bk], 1);
        if (writeIdx) out[(size_t)ZQ_ELEMS + 2 + n0 + m] = (float)bk;
    }
    __syncthreads();

    // ---- z_q gather + straight-through fl(z + fl(e - z)) + SSE ----
    const int w = tid >> 5, lane = tid & 31;
    float lsse = 0.f;
    float* zqout = out + (size_t)b * (CDIM * SPB) + s0;
    for (int p = 0; p < 8; p++) {
        __syncthreads();
#pragma unroll
        for (int r = 0; r < 16; r++) {
            int m = w * 16 + r;
            Ebuf[lane * EPAD + m] = emb[(size_t)sIdx[m] * CDIM + p * 32 + lane];
        }
        __syncthreads();
#pragma unroll
        for (int j = 0; j < 16; j++) {
            int id = tid + 256 * j;
            int cc = id >> 7, m = id & 127;
            float v  = Ebuf[cc * EPAD + m];
            int c = p * 32 + cc;
            float zv = Zs[c * BLK_M + m];
            float diff = __fsub_rn(v, zv);           // z_q - zp, single rounding
            lsse = fmaf(diff, diff, lsse);
            zqout[(size_t)c * SPB + m] = __fadd_rn(zv, diff);  // zp + sg(z_q - zp)
        }
    }
#pragma unroll
    for (int o = 16; o > 0; o >>= 1) lsse += __shfl_xor_sync(0xffffffffu, lsse, o);
    __syncthreads();
    if (lane == 0) red[w] = lsse;
    __syncthreads();
    if (tid == 0) {
        float s = 0.f;
        for (int i = 0; i < 8; i++) s += red[i];
        atomicAdd(&g_sse, s);
    }

    // ---- fused finalize: last-finishing block computes loss + perplexity ----
    if (!writeScalars) return;
    __shared__ int sLast;
    if (tid == 0) {
        __threadfence();
        sLast = (atomicAdd(&g_done, 1) == (int)gridDim.x - 1);
    }
    __syncthreads();
    if (!sLast) return;
    float h = 0.f;
#pragma unroll
    for (int q = 0; q < 4; q++) {
        float c = (float)g_counts[tid + 256 * q];
        float e = c * (1.0f / 32768.0f);
        h += e * logf(e + 1e-10f);
    }
#pragma unroll
    for (int o = 16; o > 0; o >>= 1) h += __shfl_xor_sync(0xffffffffu, h, o);
    if (lane == 0) red[w] = h;
    __syncthreads();
    if (tid == 0) {
        float v = 0.f;
        for (int i = 0; i < 8; i++) v += red[i];
        // LEGACY loss = mse + 0.25*mse = 1.25*mse
        out[ZQ_ELEMS]     = 1.25f * g_sse * (1.0f / 8388608.0f);
        out[ZQ_ELEMS + 1] = expf(-v);
        g_done = 0;                       // reset for deterministic graph replay
    }
}

// ---------------------------------------------------------------------------
extern "C" void kernel_launch(void* const* d_in, const int* in_sizes, int n_in,
                              void* d_out, int out_size) {
    const float* z   = (const float*)d_in[0];
    const float* emb = (const float*)d_in[1];
    if (n_in >= 2 && in_sizes[0] == KCODES * CDIM && in_sizes[1] == ZQ_ELEMS) {
        // defensive: inputs arrived swapped
        z   = (const float*)d_in[1];
        emb = (const float*)d_in[0];
    }
    float* out = (float*)d_out;
    int writeScalars = out_size >= ZQ_ELEMS + 2;
    int writeIdx     = out_size >= ZQ_ELEMS + 2 + NROWS;

    size_t smem = SMEM_FLOATS * sizeof(float);   // 153640 B
    cudaFuncSetAttribute(vq_main_kernel,
                         cudaFuncAttributeMaxDynamicSharedMemorySize, (int)smem);

    bias_kernel<<<64, 256>>>(emb);
    vq_main_kernel<<<NROWS / BLK_M, 256, smem>>>(z, emb, out, writeIdx, writeScalars);
}

// round 13
// speedup vs baseline: 1.7344x; 1.7344x over previous
#include <cuda_runtime.h>
#include <math.h>

#define NROWS     32768
#define CDIM      256
#define KCODES    1024
#define BLK_M     128
#define SPB       4096          // spatial positions per batch element (16*16*16)
#define ZQ_ELEMS  8388608       // 8*256*4096
#define EPAD      132           // padded row stride for E-tile in smem
#define EBUF_OFF  32768         // Zs = 256*128 floats
#define EBUF_HALF 4224          // one E buffer = 32*132 floats
#define SMEM_FLOATS (32768 + 2*4224 + 128 + 128)  // Zs + 2xEbuf + sIdx + aRow

__device__ float g_b2[KCODES];      // sum e_k^2, strict sequential rounding
__device__ int   g_counts[KCODES];
__device__ float g_sse;

// ---- packed fp32x2 helpers (Blackwell dual-rate fp32 pipe) --------------
__device__ __forceinline__ unsigned long long pk2(float x) {
    unsigned long long r;
    asm("mov.b64 %0, {%1, %1};" : "=l"(r) : "f"(x));
    return r;
}
__device__ __forceinline__ void fma2(unsigned long long& d,
                                     unsigned long long a, unsigned long long b) {
    asm("fma.rn.f32x2 %0, %1, %2, %0;" : "+l"(d) : "l"(a), "l"(b));
}
__device__ __forceinline__ void upk(unsigned long long v, float& lo, float& hi) {
    asm("mov.b64 {%0, %1}, %2;" : "=f"(lo), "=f"(hi) : "l"(v));
}

// ---------------------------------------------------------------------------
// Kernel 1: b_k = sum_c fl(fl(e^2)+...) sequential ascending c (strict, no fma)
// 64 blocks x 256 threads, 16 codes per block; coalesced stage, padded smem.
// ---------------------------------------------------------------------------
__global__ void bias_kernel(const float* __restrict__ emb) {
    __shared__ float sb[16 * 257];
    const int tid = threadIdx.x;
    const int k0 = blockIdx.x * 16;
    // coalesced load of 16 rows (4096 floats) into padded smem
    const float4* src = (const float4*)(emb + (size_t)k0 * CDIM);
    for (int i = tid; i < 1024; i += 256) {
        float4 v = src[i];
        int r = i >> 6, c = (i & 63) * 4;   // 64 float4 per row
        float* d = &sb[r * 257 + c];
        d[0] = v.x; d[1] = v.y; d[2] = v.z; d[3] = v.w;
    }
    __syncthreads();
    if (tid < 16) {
        const float* e = &sb[tid * 257];
        float s = 0.f;
        for (int c = 0; c < CDIM; c++)
            s = __fadd_rn(s, __fmul_rn(e[c], e[c]));
        g_b2[k0 + tid] = s;
    }
    for (int k = tid; k < 16; k += 256) g_counts[k0 + k] = 0;
    if (tid == 16 && blockIdx.x == 0) g_sse = 0.f;
}

// ---------------------------------------------------------------------------
// Kernel 2: main — distance GEMM (FFMA2) + argmin + gather z_q + SSE + counts
// (byte-identical to the 397.1us Round-4 kernel)
// ---------------------------------------------------------------------------
__global__ __launch_bounds__(256, 1)
void vq_main_kernel(const float* __restrict__ z, const float* __restrict__ emb,
                    float* __restrict__ out, int writeIdx) {
    extern __shared__ float sm[];
    float* Zs   = sm;                       // [256 c][128 m]
    float* Ebuf = sm + EBUF_OFF;            // 2 x [32 cc][132]
    int*   sIdx = (int*)(sm + EBUF_OFF + 2 * EBUF_HALF);
    float* aRow = sm + EBUF_OFF + 2 * EBUF_HALF + 128;

    const int tid = threadIdx.x;
    const int tx = tid & 15, ty = tid >> 4;
    const int n0 = blockIdx.x * BLK_M;
    const int b  = n0 >> 12;
    const int s0 = n0 & (SPB - 1);
    const float* zb = z + (size_t)b * (CDIM * SPB) + s0;

    // ---- load Z tile into smem (transposed to [c][m]), coalesced ----
    {
        int lane4 = (tid & 31) * 4;
        for (int c = tid >> 5; c < CDIM; c += 8) {
            float4 v = *(const float4*)(zb + (size_t)c * SPB + lane4);
            *(float4*)&Zs[c * BLK_M + lane4] = v;
        }
    }
    __syncthreads();

    // ---- a_m = sum_c fl(fl(z^2)+...) sequential ascending c (strict) ----
    if (tid < BLK_M) {
        float s = 0.f;
        for (int c = 0; c < CDIM; c++) {
            float v = Zs[c * BLK_M + tid];
            s = __fadd_rn(s, __fmul_rn(v, v));
        }
        aRow[tid] = s;
    }
    __syncthreads();

    float av[8];
#pragma unroll
    for (int i = 0; i < 8; i++) {
        int m = (i < 4) ? (ty * 4 + i) : (64 + ty * 4 + i - 4);
        av[i] = aRow[m];
    }

    float bestv[8];
    int   bestk[8];
#pragma unroll
    for (int i = 0; i < 8; i++) { bestv[i] = 3.4e38f; bestk[i] = 0; }

    const int cc0 = tid & 31, kk0 = tid >> 5;
    float er[16];
    {   // prefetch E chunk (ktile 0, cchunk 0)
        const float* ep = emb + (size_t)kk0 * CDIM + cc0;
#pragma unroll
        for (int i = 0; i < 16; i++) er[i] = ep[(size_t)(8 * i) * CDIM];
    }

    for (int kt = 0; kt < 8; kt++) {
        unsigned long long acc2[4][8];   // (row pair) x (8 k-cols), packed fp32x2
#pragma unroll
        for (int p = 0; p < 4; p++)
#pragma unroll
            for (int j = 0; j < 8; j++) acc2[p][j] = 0ull;

        for (int ch = 0; ch < 8; ch++) {
            const int gch = kt * 8 + ch;
            float* cur = Ebuf + (gch & 1) * EBUF_HALF;
            // stage this chunk into its parity buffer (peers done reading it)
#pragma unroll
            for (int i = 0; i < 16; i++) cur[cc0 * EPAD + kk0 + 8 * i] = er[i];
            __syncthreads();
            int nch = ch + 1, nkt = kt;
            if (nch == 8) { nch = 0; nkt++; }
            if (nkt < 8) {
                const float* ep = emb + (size_t)(nkt * 128 + kk0) * CDIM + nch * 32 + cc0;
#pragma unroll
                for (int i = 0; i < 16; i++) er[i] = ep[(size_t)(8 * i) * CDIM];
            }
            const int cbase = ch * 32;
#pragma unroll
            for (int cc = 0; cc < 32; cc++) {
                const float* zrow = &Zs[(cbase + cc) * BLK_M];
                ulonglong2 z0 = *(const ulonglong2*)(zrow + ty * 4);        // rows i0..i3
                ulonglong2 z1 = *(const ulonglong2*)(zrow + 64 + ty * 4);   // rows i4..i7
                float4 e0 = *(const float4*)&cur[cc * EPAD + tx * 4];
                float4 e1 = *(const float4*)&cur[cc * EPAD + 64 + tx * 4];
                unsigned long long eb2[8] = {
                    pk2(e0.x), pk2(e0.y), pk2(e0.z), pk2(e0.w),
                    pk2(e1.x), pk2(e1.y), pk2(e1.z), pk2(e1.w)};
#pragma unroll
                for (int j = 0; j < 8; j++) {
                    fma2(acc2[0][j], z0.x, eb2[j]);
                    fma2(acc2[1][j], z0.y, eb2[j]);
                    fma2(acc2[2][j], z1.x, eb2[j]);
                    fma2(acc2[3][j], z1.y, eb2[j]);
                }
            }
        }
        // ---- unpack + fold: d = fl(fl(a+b_k) - fl(2*dot)), argmin ----
        const int k0 = kt * 128;
        float bj[8];
#pragma unroll
        for (int j = 0; j < 8; j++) {
            int kl = (j < 4) ? (tx * 4 + j) : (64 + tx * 4 + j - 4);
            bj[j] = g_b2[k0 + kl];
        }
#pragma unroll
        for (int p = 0; p < 4; p++) {
#pragma unroll
            for (int j = 0; j < 8; j++) {
                float dlo, dhi;
                upk(acc2[p][j], dlo, dhi);
                int i0 = 2 * p, i1 = 2 * p + 1;
                int kl = (j < 4) ? (tx * 4 + j) : (64 + tx * 4 + j - 4);
                float t0 = __fadd_rn(av[i0], bj[j]);
                float d0 = __fsub_rn(t0, __fadd_rn(dlo, dlo));
                if (d0 < bestv[i0]) { bestv[i0] = d0; bestk[i0] = k0 + kl; }
                float t1 = __fadd_rn(av[i1], bj[j]);
                float d1 = __fsub_rn(t1, __fadd_rn(dhi, dhi));
                if (d1 < bestv[i1]) { bestv[i1] = d1; bestk[i1] = k0 + kl; }
            }
        }
    }

    // ---- reduce argmin across the 16 tx threads of each row ----
    float* rv = Ebuf;
    int*   rk = (int*)(Ebuf + 2048);
    __syncthreads();
#pragma unroll
    for (int i = 0; i < 8; i++) {
        int m = (i < 4) ? (ty * 4 + i) : (64 + ty * 4 + i - 4);
        rv[m * 16 + tx] = bestv[i];
        rk[m * 16 + tx] = bestk[i];
    }
    __syncthreads();
    if (tid < BLK_M) {
        int m = tid;
        float bv = 3.4e38f; int bk = KCODES;
        for (int i = 0; i < 16; i++) {
            float v = rv[m * 16 + i]; int k = rk[m * 16 + i];
            if (v < bv || (v == bv && k < bk)) { bv = v; bk = k; }
        }
        sIdx[m] = bk;
        atomicAdd(&g_counts[bk], 1);
        if (writeIdx) out[(size_t)ZQ_ELEMS + 2 + n0 + m] = (float)bk;
    }
    __syncthreads();

    // ---- z_q gather + straight-through fl(z + fl(e - z)) + SSE ----
    const int w = tid >> 5, lane = tid & 31;
    float lsse = 0.f;
    float* zqout = out + (size_t)b * (CDIM * SPB) + s0;
    for (int p = 0; p < 8; p++) {
        __syncthreads();
#pragma unroll
        for (int r = 0; r < 16; r++) {
            int m = w * 16 + r;
            Ebuf[lane * EPAD + m] = emb[(size_t)sIdx[m] * CDIM + p * 32 + lane];
        }
        __syncthreads();
#pragma unroll
        for (int j = 0; j < 16; j++) {
            int id = tid + 256 * j;
            int cc = id >> 7, m = id & 127;
            float v  = Ebuf[cc * EPAD + m];
            int c = p * 32 + cc;
            float zv = Zs[c * BLK_M + m];
            float diff = __fsub_rn(v, zv);           // z_q - zp, single rounding
            lsse = fmaf(diff, diff, lsse);
            zqout[(size_t)c * SPB + m] = __fadd_rn(zv, diff);  // zp + sg(z_q - zp)
        }
    }
#pragma unroll
    for (int o = 16; o > 0; o >>= 1) lsse += __shfl_xor_sync(0xffffffffu, lsse, o);
    __syncthreads();
    if (lane == 0) Ebuf[w] = lsse;
    __syncthreads();
    if (tid == 0) {
        float s = 0.f;
        for (int i = 0; i < 8; i++) s += Ebuf[i];
        atomicAdd(&g_sse, s);
    }
}

// ---------------------------------------------------------------------------
// Kernel 3: loss + perplexity scalars
// ---------------------------------------------------------------------------
__global__ void finalize_kernel(float* __restrict__ out) {
    __shared__ float red[32];
    int t = threadIdx.x;                       // 1024 threads
    float c = (float)g_counts[t];
    float e = c * (1.0f / 32768.0f);
    float h = e * logf(e + 1e-10f);
#pragma unroll
    for (int o = 16; o > 0; o >>= 1) h += __shfl_xor_sync(0xffffffffu, h, o);
    if ((t & 31) == 0) red[t >> 5] = h;
    __syncthreads();
    if (t < 32) {
        float v = red[t];
#pragma unroll
        for (int o = 16; o > 0; o >>= 1) v += __shfl_xor_sync(0xffffffffu, v, o);
        if (t == 0) {
            // LEGACY loss = mse + 0.25*mse = 1.25*mse
            out[ZQ_ELEMS]     = 1.25f * g_sse * (1.0f / 8388608.0f);
            out[ZQ_ELEMS + 1] = expf(-v);
        }
    }
}

// ---------------------------------------------------------------------------
extern "C" void kernel_launch(void* const* d_in, const int* in_sizes, int n_in,
                              void* d_out, int out_size) {
    const float* z   = (const float*)d_in[0];
    const float* emb = (const float*)d_in[1];
    if (n_in >= 2 && in_sizes[0] == KCODES * CDIM && in_sizes[1] == ZQ_ELEMS) {
        // defensive: inputs arrived swapped
        z   = (const float*)d_in[1];
        emb = (const float*)d_in[0];
    }
    float* out = (float*)d_out;
    int writeScalars = out_size >= ZQ_ELEMS + 2;
    int writeIdx     = out_size >= ZQ_ELEMS + 2 + NROWS;

    size_t smem = SMEM_FLOATS * sizeof(float);   // 165888 B
    cudaFuncSetAttribute(vq_main_kernel,
                         cudaFuncAttributeMaxDynamicSharedMemorySize, (int)smem);

    bias_kernel<<<64, 256>>>(emb);
    vq_main_kernel<<<NROWS / BLK_M, 256, smem>>>(z, emb, out, writeIdx);
    if (writeScalars) finalize_kernel<<<1, 1024>>>(out);
}

// round 14
// speedup vs baseline: 1.7563x; 1.0127x over previous
#include <cuda_runtime.h>
#include <math.h>

#define NROWS     32768
#define CDIM      256
#define KCODES    1024
#define BLK_M     128
#define SPB       4096          // spatial positions per batch element (16*16*16)
#define ZQ_ELEMS  8388608       // 8*256*4096
#define EPAD      132           // padded row stride for E-tile in smem
#define EBUF_OFF  32768         // Zs = 256*128 floats
#define EBUF_HALF 4224          // one E buffer = 32*132 floats
#define SMEM_FLOATS (32768 + 2*4224 + 128)  // Zs + 2xEbuf + aRow

#define SPLIT2_TILES 176        // tiles 0..175: 2 units (4+4 kt)
#define GRID_A 592              // 176*2 + 80*3 = 4*148 exactly

__device__ float  g_b2[KCODES];     // sum e_k^2, strict sequential rounding
__device__ float  gA[NROWS];        // sum z^2 per row, strict sequential rounding
__device__ float2 gCand[256 * 3 * BLK_M];
__device__ int    g_counts[KCODES];
__device__ float  g_sse;
__device__ int    g_done;

// ---- packed fp32x2 helpers (Blackwell dual-rate fp32 pipe) --------------
__device__ __forceinline__ unsigned long long pk2(float x) {
    unsigned long long r;
    asm("mov.b64 %0, {%1, %1};" : "=l"(r) : "f"(x));
    return r;
}
__device__ __forceinline__ void fma2(unsigned long long& d,
                                     unsigned long long a, unsigned long long b) {
    asm("fma.rn.f32x2 %0, %1, %2, %0;" : "+l"(d) : "l"(a), "l"(b));
}
__device__ __forceinline__ void upk(unsigned long long v, float& lo, float& hi) {
    asm("mov.b64 {%0, %1}, %2;" : "=f"(lo), "=f"(hi) : "l"(v));
}
__device__ __forceinline__ bool better(float v1, int k1, float v2, int k2) {
    return v1 < v2 || (v1 == v2 && k1 < k2);
}

// ---------------------------------------------------------------------------
// Kernel 1: b_k = sum_c fl(fl(e^2)+...) sequential ascending c (strict, no fma)
// ---------------------------------------------------------------------------
__global__ void bias_kernel(const float* __restrict__ emb) {
    __shared__ float sb[16 * 257];
    const int tid = threadIdx.x;
    const int k0 = blockIdx.x * 16;
    const float4* src = (const float4*)(emb + (size_t)k0 * CDIM);
    for (int i = tid; i < 1024; i += 256) {
        float4 v = src[i];
        int r = i >> 6, c = (i & 63) * 4;
        float* d = &sb[r * 257 + c];
        d[0] = v.x; d[1] = v.y; d[2] = v.z; d[3] = v.w;
    }
    __syncthreads();
    if (tid < 16) {
        const float* e = &sb[tid * 257];
        float s = 0.f;
        for (int c = 0; c < CDIM; c++)
            s = __fadd_rn(s, __fmul_rn(e[c], e[c]));
        g_b2[k0 + tid] = s;
    }
    for (int k = tid; k < 16; k += 256) g_counts[k0 + k] = 0;
    if (tid == 16 && blockIdx.x == 0) { g_sse = 0.f; g_done = 0; }
}

// ---------------------------------------------------------------------------
// Kernel 1b: a_n = sum_c fl(fl(z^2)+...) sequential ascending c (strict)
// Same chain order as the old in-block aRow compute -> bit-identical.
// ---------------------------------------------------------------------------
__global__ void prep_a_kernel(const float* __restrict__ z) {
    int row = blockIdx.x * 256 + threadIdx.x;     // 128 blocks x 256 rows
    int b = row >> 12, s = row & (SPB - 1);
    const float* p = z + (size_t)b * (CDIM * SPB) + s;
    float acc = 0.f;
    for (int c = 0; c < CDIM; c++) {
        float v = p[(size_t)c * SPB];
        acc = __fadd_rn(acc, __fmul_rn(v, v));
    }
    gA[row] = acc;
}

// ---------------------------------------------------------------------------
// Kernel 2: GEMM units — (tile, kt-range) -> per-row candidate (d, k)
// Mainloop body identical to the 397us R4/R13 kernel; only kt bounds differ.
// ---------------------------------------------------------------------------
__global__ __launch_bounds__(256, 1)
void vq_gemm_kernel(const float* __restrict__ z, const float* __restrict__ emb) {
    extern __shared__ float sm[];
    float* Zs   = sm;                       // [256 c][128 m]
    float* Ebuf = sm + EBUF_OFF;            // 2 x [32 cc][132]
    float* aRow = sm + EBUF_OFF + 2 * EBUF_HALF;

    const int bid = blockIdx.x;
    int tile, unit, kt0, kt1;
    if (bid < 2 * SPLIT2_TILES) {
        tile = bid >> 1; unit = bid & 1;
        kt0 = unit * 4; kt1 = kt0 + 4;
    } else {
        int u = bid - 2 * SPLIT2_TILES;
        tile = SPLIT2_TILES + u / 3; unit = u % 3;
        kt0 = (unit == 0) ? 0 : (unit == 1 ? 3 : 6);
        kt1 = (unit < 2) ? kt0 + 3 : 8;
    }

    const int tid = threadIdx.x;
    const int tx = tid & 15, ty = tid >> 4;
    const int n0 = tile * BLK_M;
    const int b  = n0 >> 12;
    const int s0 = n0 & (SPB - 1);
    const float* zb = z + (size_t)b * (CDIM * SPB) + s0;

    // ---- load Z tile into smem (transposed to [c][m]), coalesced ----
    {
        int lane4 = (tid & 31) * 4;
        for (int c = tid >> 5; c < CDIM; c += 8) {
            float4 v = *(const float4*)(zb + (size_t)c * SPB + lane4);
            *(float4*)&Zs[c * BLK_M + lane4] = v;
        }
    }
    if (tid < BLK_M) aRow[tid] = gA[n0 + tid];
    __syncthreads();

    float av[8];
#pragma unroll
    for (int i = 0; i < 8; i++) {
        int m = (i < 4) ? (ty * 4 + i) : (64 + ty * 4 + i - 4);
        av[i] = aRow[m];
    }

    float bestv[8];
    int   bestk[8];
#pragma unroll
    for (int i = 0; i < 8; i++) { bestv[i] = 3.4e38f; bestk[i] = KCODES; }

    const int cc0 = tid & 31, kk0 = tid >> 5;
    float er[16];
    {   // prefetch E chunk (ktile kt0, cchunk 0)
        const float* ep = emb + (size_t)(kt0 * 128 + kk0) * CDIM + cc0;
#pragma unroll
        for (int i = 0; i < 16; i++) er[i] = ep[(size_t)(8 * i) * CDIM];
    }

    for (int kt = kt0; kt < kt1; kt++) {
        unsigned long long acc2[4][8];   // (row pair) x (8 k-cols), packed fp32x2
#pragma unroll
        for (int p = 0; p < 4; p++)
#pragma unroll
            for (int j = 0; j < 8; j++) acc2[p][j] = 0ull;

        for (int ch = 0; ch < 8; ch++) {
            const int gch = kt * 8 + ch;
            float* cur = Ebuf + (gch & 1) * EBUF_HALF;
            // stage this chunk into its parity buffer (peers done reading it)
#pragma unroll
            for (int i = 0; i < 16; i++) cur[cc0 * EPAD + kk0 + 8 * i] = er[i];
            __syncthreads();
            int nch = ch + 1, nkt = kt;
            if (nch == 8) { nch = 0; nkt++; }
            if (nkt < kt1) {
                const float* ep = emb + (size_t)(nkt * 128 + kk0) * CDIM + nch * 32 + cc0;
#pragma unroll
                for (int i = 0; i < 16; i++) er[i] = ep[(size_t)(8 * i) * CDIM];
            }
            const int cbase = ch * 32;
#pragma unroll
            for (int cc = 0; cc < 32; cc++) {
                const float* zrow = &Zs[(cbase + cc) * BLK_M];
                ulonglong2 z0 = *(const ulonglong2*)(zrow + ty * 4);        // rows i0..i3
                ulonglong2 z1 = *(const ulonglong2*)(zrow + 64 + ty * 4);   // rows i4..i7
                float4 e0 = *(const float4*)&cur[cc * EPAD + tx * 4];
                float4 e1 = *(const float4*)&cur[cc * EPAD + 64 + tx * 4];
                unsigned long long eb2[8] = {
                    pk2(e0.x), pk2(e0.y), pk2(e0.z), pk2(e0.w),
                    pk2(e1.x), pk2(e1.y), pk2(e1.z), pk2(e1.w)};
#pragma unroll
                for (int j = 0; j < 8; j++) {
                    fma2(acc2[0][j], z0.x, eb2[j]);
                    fma2(acc2[1][j], z0.y, eb2[j]);
                    fma2(acc2[2][j], z1.x, eb2[j]);
                    fma2(acc2[3][j], z1.y, eb2[j]);
                }
            }
        }
        // ---- unpack + fold: d = fl(fl(a+b_k) - fl(2*dot)), argmin ----
        const int k0 = kt * 128;
        float bj[8];
#pragma unroll
        for (int j = 0; j < 8; j++) {
            int kl = (j < 4) ? (tx * 4 + j) : (64 + tx * 4 + j - 4);
            bj[j] = g_b2[k0 + kl];
        }
#pragma unroll
        for (int p = 0; p < 4; p++) {
#pragma unroll
            for (int j = 0; j < 8; j++) {
                float dlo, dhi;
                upk(acc2[p][j], dlo, dhi);
                int i0 = 2 * p, i1 = 2 * p + 1;
                int kl = (j < 4) ? (tx * 4 + j) : (64 + tx * 4 + j - 4);
                float t0 = __fadd_rn(av[i0], bj[j]);
                float d0 = __fsub_rn(t0, __fadd_rn(dlo, dlo));
                if (d0 < bestv[i0]) { bestv[i0] = d0; bestk[i0] = k0 + kl; }
                float t1 = __fadd_rn(av[i1], bj[j]);
                float d1 = __fsub_rn(t1, __fadd_rn(dhi, dhi));
                if (d1 < bestv[i1]) { bestv[i1] = d1; bestk[i1] = k0 + kl; }
            }
        }
    }

    // ---- reduce argmin across the 16 tx threads of each row; emit candidate ----
    float* rv = Ebuf;
    int*   rk = (int*)(Ebuf + 2048);
    __syncthreads();
#pragma unroll
    for (int i = 0; i < 8; i++) {
        int m = (i < 4) ? (ty * 4 + i) : (64 + ty * 4 + i - 4);
        rv[m * 16 + tx] = bestv[i];
        rk[m * 16 + tx] = bestk[i];
    }
    __syncthreads();
    if (tid < BLK_M) {
        float bv = 3.4e38f; int bk = KCODES;
        for (int i = 0; i < 16; i++) {
            float v = rv[tid * 16 + i]; int k = rk[tid * 16 + i];
            if (v < bv || (v == bv && k < bk)) { bv = v; bk = k; }
        }
        gCand[(tile * 3 + unit) * BLK_M + tid] = make_float2(bv, __int_as_float(bk));
    }
}

// ---------------------------------------------------------------------------
// Kernel 3: merge candidates + gather z_q + SSE + counts + fused finalize
// ---------------------------------------------------------------------------
__global__ __launch_bounds__(256, 1)
void vq_epi_kernel(const float* __restrict__ z, const float* __restrict__ emb,
                   float* __restrict__ out, int writeIdx, int writeScalars) {
    __shared__ int   sIdx[BLK_M];
    __shared__ float Ebuf[EBUF_HALF];
    __shared__ float red[8];
    __shared__ int   sLast;

    const int tile = blockIdx.x;
    const int tid = threadIdx.x;
    const int w = tid >> 5, lane = tid & 31;
    const int n0 = tile * BLK_M;
    const int b  = n0 >> 12;
    const int s0 = n0 & (SPB - 1);
    const float* zb = z + (size_t)b * (CDIM * SPB) + s0;

    if (tid < BLK_M) {
        int nu = (tile < SPLIT2_TILES) ? 2 : 3;
        float bv = 3.4e38f; int bk = KCODES;
        for (int u = 0; u < nu; u++) {
            float2 cnd = gCand[(tile * 3 + u) * BLK_M + tid];
            int k = __float_as_int(cnd.y);
            if (better(cnd.x, k, bv, bk)) { bv = cnd.x; bk = k; }
        }
        sIdx[tid] = bk;
        atomicAdd(&g_counts[bk], 1);
        if (writeIdx) out[(size_t)ZQ_ELEMS + 2 + n0 + tid] = (float)bk;
    }
    __syncthreads();

    // ---- z_q gather + straight-through fl(z + fl(e - z)) + SSE ----
    float lsse = 0.f;
    float* zqout = out + (size_t)b * (CDIM * SPB) + s0;
    for (int p = 0; p < 8; p++) {
#pragma unroll
        for (int r = 0; r < 16; r++) {
            int m = w * 16 + r;
            Ebuf[lane * EPAD + m] = emb[(size_t)sIdx[m] * CDIM + p * 32 + lane];
        }
        __syncthreads();
#pragma unroll
        for (int j = 0; j < 16; j++) {
            int id = tid + 256 * j;
            int cc = id >> 7, m = id & 127;
            float v  = Ebuf[cc * EPAD + m];
            int c = p * 32 + cc;
            float zv = zb[(size_t)c * SPB + m];
            float diff = __fsub_rn(v, zv);           // z_q - zp, single rounding
            lsse = fmaf(diff, diff, lsse);
            zqout[(size_t)c * SPB + m] = __fadd_rn(zv, diff);  // zp + sg(z_q - zp)
        }
        __syncthreads();
    }
#pragma unroll
    for (int o = 16; o > 0; o >>= 1) lsse += __shfl_xor_sync(0xffffffffu, lsse, o);
    if (lane == 0) red[w] = lsse;
    __syncthreads();
    if (tid == 0) {
        float s = 0.f;
        for (int i = 0; i < 8; i++) s += red[i];
        atomicAdd(&g_sse, s);
    }

    // ---- fused finalize: last-finishing block computes loss + perplexity ----
    if (!writeScalars) return;
    if (tid == 0) {
        __threadfence();
        sLast = (atomicAdd(&g_done, 1) == (int)gridDim.x - 1);
    }
    __syncthreads();
    if (!sLast) return;
    float h = 0.f;
#pragma unroll
    for (int q = 0; q < 4; q++) {
        float c = (float)g_counts[tid + 256 * q];
        float e = c * (1.0f / 32768.0f);
        h += e * logf(e + 1e-10f);
    }
#pragma unroll
    for (int o = 16; o > 0; o >>= 1) h += __shfl_xor_sync(0xffffffffu, h, o);
    if (lane == 0) red[w] = h;
    __syncthreads();
    if (tid == 0) {
        float v = 0.f;
        for (int i = 0; i < 8; i++) v += red[i];
        // LEGACY loss = mse + 0.25*mse = 1.25*mse
        out[ZQ_ELEMS]     = 1.25f * g_sse * (1.0f / 8388608.0f);
        out[ZQ_ELEMS + 1] = expf(-v);
        g_done = 0;                       // reset for deterministic graph replay
    }
}

// ---------------------------------------------------------------------------
extern "C" void kernel_launch(void* const* d_in, const int* in_sizes, int n_in,
                              void* d_out, int out_size) {
    const float* z   = (const float*)d_in[0];
    const float* emb = (const float*)d_in[1];
    if (n_in >= 2 && in_sizes[0] == KCODES * CDIM && in_sizes[1] == ZQ_ELEMS) {
        // defensive: inputs arrived swapped
        z   = (const float*)d_in[1];
        emb = (const float*)d_in[0];
    }
    float* out = (float*)d_out;
    int writeScalars = out_size >= ZQ_ELEMS + 2;
    int writeIdx     = out_size >= ZQ_ELEMS + 2 + NROWS;

    size_t smem = SMEM_FLOATS * sizeof(float);   // 165376 B
    cudaFuncSetAttribute(vq_gemm_kernel,
                         cudaFuncAttributeMaxDynamicSharedMemorySize, (int)smem);

    bias_kernel<<<64, 256>>>(emb);
    prep_a_kernel<<<128, 256>>>(z);
    vq_gemm_kernel<<<GRID_A, 256, smem>>>(z, emb);
    vq_epi_kernel<<<NROWS / BLK_M, 256>>>(z, emb, out, writeIdx, writeScalars);
}

// round 15
// speedup vs baseline: 1.7595x; 1.0018x over previous
#include <cuda_runtime.h>
#include <math.h>

#define NROWS     32768
#define CDIM      256
#define KCODES    1024
#define BLK_M     128
#define SPB       4096          // spatial positions per batch element (16*16*16)
#define ZQ_ELEMS  8388608       // 8*256*4096
#define EPAD      132           // padded row stride for E-tile in smem
#define EBUF_OFF  32768         // Zs = 256*128 floats
#define EBUF_HALF 4224          // one E buffer = 32*132 floats
#define SMEM_FLOATS (32768 + 2*4224 + 128)  // Zs + 2xEbuf + aRow

#define SPLIT2_TILES 176        // tiles 0..175: 2 units (4+4 kt)
#define GRID_A 592              // 176*2 + 80*3 = 4*148 exactly
#define GRID_G 2048             // 256 tiles x 8 channel-passes

__device__ float  g_b2[KCODES];     // sum e_k^2, strict sequential rounding
__device__ float  gA[NROWS];        // sum z^2 per row, strict sequential rounding
__device__ float2 gCand[256 * 3 * BLK_M];
__device__ int    gIdx[NROWS];
__device__ int    g_counts[KCODES];
__device__ float  g_sse;
__device__ int    g_done;

// ---- packed fp32x2 helpers (Blackwell dual-rate fp32 pipe) --------------
__device__ __forceinline__ unsigned long long pk2(float x) {
    unsigned long long r;
    asm("mov.b64 %0, {%1, %1};" : "=l"(r) : "f"(x));
    return r;
}
__device__ __forceinline__ void fma2(unsigned long long& d,
                                     unsigned long long a, unsigned long long b) {
    asm("fma.rn.f32x2 %0, %1, %2, %0;" : "+l"(d) : "l"(a), "l"(b));
}
__device__ __forceinline__ void upk(unsigned long long v, float& lo, float& hi) {
    asm("mov.b64 {%0, %1}, %2;" : "=f"(lo), "=f"(hi) : "l"(v));
}
__device__ __forceinline__ bool better(float v1, int k1, float v2, int k2) {
    return v1 < v2 || (v1 == v2 && k1 < k2);
}

// ---------------------------------------------------------------------------
// Kernel 1: b_k = sum_c fl(fl(e^2)+...) sequential ascending c (strict, no fma)
// ---------------------------------------------------------------------------
__global__ void bias_kernel(const float* __restrict__ emb) {
    __shared__ float sb[16 * 257];
    const int tid = threadIdx.x;
    const int k0 = blockIdx.x * 16;
    const float4* src = (const float4*)(emb + (size_t)k0 * CDIM);
    for (int i = tid; i < 1024; i += 256) {
        float4 v = src[i];
        int r = i >> 6, c = (i & 63) * 4;
        float* d = &sb[r * 257 + c];
        d[0] = v.x; d[1] = v.y; d[2] = v.z; d[3] = v.w;
    }
    __syncthreads();
    if (tid < 16) {
        const float* e = &sb[tid * 257];
        float s = 0.f;
        for (int c = 0; c < CDIM; c++)
            s = __fadd_rn(s, __fmul_rn(e[c], e[c]));
        g_b2[k0 + tid] = s;
    }
    for (int k = tid; k < 16; k += 256) g_counts[k0 + k] = 0;
    if (tid == 16 && blockIdx.x == 0) { g_sse = 0.f; g_done = 0; }
}

// ---------------------------------------------------------------------------
// Kernel 1b: a_n = sum_c fl(fl(z^2)+...) sequential ascending c (strict)
// ---------------------------------------------------------------------------
__global__ void prep_a_kernel(const float* __restrict__ z) {
    int row = blockIdx.x * 256 + threadIdx.x;     // 128 blocks x 256 rows
    int b = row >> 12, s = row & (SPB - 1);
    const float* p = z + (size_t)b * (CDIM * SPB) + s;
    float acc = 0.f;
    for (int c = 0; c < CDIM; c++) {
        float v = p[(size_t)c * SPB];
        acc = __fadd_rn(acc, __fmul_rn(v, v));
    }
    gA[row] = acc;
}

// ---------------------------------------------------------------------------
// Kernel 2: GEMM units — (tile, kt-range) -> per-row candidate (d, k)
// (byte-identical to the R14 kernel)
// ---------------------------------------------------------------------------
__global__ __launch_bounds__(256, 1)
void vq_gemm_kernel(const float* __restrict__ z, const float* __restrict__ emb) {
    extern __shared__ float sm[];
    float* Zs   = sm;                       // [256 c][128 m]
    float* Ebuf = sm + EBUF_OFF;            // 2 x [32 cc][132]
    float* aRow = sm + EBUF_OFF + 2 * EBUF_HALF;

    const int bid = blockIdx.x;
    int tile, unit, kt0, kt1;
    if (bid < 2 * SPLIT2_TILES) {
        tile = bid >> 1; unit = bid & 1;
        kt0 = unit * 4; kt1 = kt0 + 4;
    } else {
        int u = bid - 2 * SPLIT2_TILES;
        tile = SPLIT2_TILES + u / 3; unit = u % 3;
        kt0 = (unit == 0) ? 0 : (unit == 1 ? 3 : 6);
        kt1 = (unit < 2) ? kt0 + 3 : 8;
    }

    const int tid = threadIdx.x;
    const int tx = tid & 15, ty = tid >> 4;
    const int n0 = tile * BLK_M;
    const int b  = n0 >> 12;
    const int s0 = n0 & (SPB - 1);
    const float* zb = z + (size_t)b * (CDIM * SPB) + s0;

    // ---- load Z tile into smem (transposed to [c][m]), coalesced ----
    {
        int lane4 = (tid & 31) * 4;
        for (int c = tid >> 5; c < CDIM; c += 8) {
            float4 v = *(const float4*)(zb + (size_t)c * SPB + lane4);
            *(float4*)&Zs[c * BLK_M + lane4] = v;
        }
    }
    if (tid < BLK_M) aRow[tid] = gA[n0 + tid];
    __syncthreads();

    float av[8];
#pragma unroll
    for (int i = 0; i < 8; i++) {
        int m = (i < 4) ? (ty * 4 + i) : (64 + ty * 4 + i - 4);
        av[i] = aRow[m];
    }

    float bestv[8];
    int   bestk[8];
#pragma unroll
    for (int i = 0; i < 8; i++) { bestv[i] = 3.4e38f; bestk[i] = KCODES; }

    const int cc0 = tid & 31, kk0 = tid >> 5;
    float er[16];
    {   // prefetch E chunk (ktile kt0, cchunk 0)
        const float* ep = emb + (size_t)(kt0 * 128 + kk0) * CDIM + cc0;
#pragma unroll
        for (int i = 0; i < 16; i++) er[i] = ep[(size_t)(8 * i) * CDIM];
    }

    for (int kt = kt0; kt < kt1; kt++) {
        unsigned long long acc2[4][8];   // (row pair) x (8 k-cols), packed fp32x2
#pragma unroll
        for (int p = 0; p < 4; p++)
#pragma unroll
            for (int j = 0; j < 8; j++) acc2[p][j] = 0ull;

        for (int ch = 0; ch < 8; ch++) {
            const int gch = kt * 8 + ch;
            float* cur = Ebuf + (gch & 1) * EBUF_HALF;
            // stage this chunk into its parity buffer (peers done reading it)
#pragma unroll
            for (int i = 0; i < 16; i++) cur[cc0 * EPAD + kk0 + 8 * i] = er[i];
            __syncthreads();
            int nch = ch + 1, nkt = kt;
            if (nch == 8) { nch = 0; nkt++; }
            if (nkt < kt1) {
                const float* ep = emb + (size_t)(nkt * 128 + kk0) * CDIM + nch * 32 + cc0;
#pragma unroll
                for (int i = 0; i < 16; i++) er[i] = ep[(size_t)(8 * i) * CDIM];
            }
            const int cbase = ch * 32;
#pragma unroll
            for (int cc = 0; cc < 32; cc++) {
                const float* zrow = &Zs[(cbase + cc) * BLK_M];
                ulonglong2 z0 = *(const ulonglong2*)(zrow + ty * 4);        // rows i0..i3
                ulonglong2 z1 = *(const ulonglong2*)(zrow + 64 + ty * 4);   // rows i4..i7
                float4 e0 = *(const float4*)&cur[cc * EPAD + tx * 4];
                float4 e1 = *(const float4*)&cur[cc * EPAD + 64 + tx * 4];
                unsigned long long eb2[8] = {
                    pk2(e0.x), pk2(e0.y), pk2(e0.z), pk2(e0.w),
                    pk2(e1.x), pk2(e1.y), pk2(e1.z), pk2(e1.w)};
#pragma unroll
                for (int j = 0; j < 8; j++) {
                    fma2(acc2[0][j], z0.x, eb2[j]);
                    fma2(acc2[1][j], z0.y, eb2[j]);
                    fma2(acc2[2][j], z1.x, eb2[j]);
                    fma2(acc2[3][j], z1.y, eb2[j]);
                }
            }
        }
        // ---- unpack + fold: d = fl(fl(a+b_k) - fl(2*dot)), argmin ----
        const int k0 = kt * 128;
        float bj[8];
#pragma unroll
        for (int j = 0; j < 8; j++) {
            int kl = (j < 4) ? (tx * 4 + j) : (64 + tx * 4 + j - 4);
            bj[j] = g_b2[k0 + kl];
        }
#pragma unroll
        for (int p = 0; p < 4; p++) {
#pragma unroll
            for (int j = 0; j < 8; j++) {
                float dlo, dhi;
                upk(acc2[p][j], dlo, dhi);
                int i0 = 2 * p, i1 = 2 * p + 1;
                int kl = (j < 4) ? (tx * 4 + j) : (64 + tx * 4 + j - 4);
                float t0 = __fadd_rn(av[i0], bj[j]);
                float d0 = __fsub_rn(t0, __fadd_rn(dlo, dlo));
                if (d0 < bestv[i0]) { bestv[i0] = d0; bestk[i0] = k0 + kl; }
                float t1 = __fadd_rn(av[i1], bj[j]);
                float d1 = __fsub_rn(t1, __fadd_rn(dhi, dhi));
                if (d1 < bestv[i1]) { bestv[i1] = d1; bestk[i1] = k0 + kl; }
            }
        }
    }

    // ---- reduce argmin across the 16 tx threads of each row; emit candidate ----
    float* rv = Ebuf;
    int*   rk = (int*)(Ebuf + 2048);
    __syncthreads();
#pragma unroll
    for (int i = 0; i < 8; i++) {
        int m = (i < 4) ? (ty * 4 + i) : (64 + ty * 4 + i - 4);
        rv[m * 16 + tx] = bestv[i];
        rk[m * 16 + tx] = bestk[i];
    }
    __syncthreads();
    if (tid < BLK_M) {
        float bv = 3.4e38f; int bk = KCODES;
        for (int i = 0; i < 16; i++) {
            float v = rv[tid * 16 + i]; int k = rk[tid * 16 + i];
            if (v < bv || (v == bv && k < bk)) { bv = v; bk = k; }
        }
        gCand[(tile * 3 + unit) * BLK_M + tid] = make_float2(bv, __int_as_float(bk));
    }
}

// ---------------------------------------------------------------------------
// Kernel 3a: merge split-K candidates -> gIdx, counts, idx output
// ---------------------------------------------------------------------------
__global__ void vq_merge_kernel(float* __restrict__ out, int writeIdx) {
    const int tile = blockIdx.x;
    const int tid = threadIdx.x;          // 128 threads = rows
    int nu = (tile < SPLIT2_TILES) ? 2 : 3;
    float bv = 3.4e38f; int bk = KCODES;
    for (int u = 0; u < nu; u++) {
        float2 cnd = gCand[(tile * 3 + u) * BLK_M + tid];
        int k = __float_as_int(cnd.y);
        if (better(cnd.x, k, bv, bk)) { bv = cnd.x; bk = k; }
    }
    int row = tile * BLK_M + tid;
    gIdx[row] = bk;
    atomicAdd(&g_counts[bk], 1);
    if (writeIdx) out[(size_t)ZQ_ELEMS + 2 + row] = (float)bk;
}

// ---------------------------------------------------------------------------
// Kernel 3b: gather z_q + straight-through + SSE; fused finalize on last block
// One block = one (tile, 32-channel pass). 2048 blocks.
// ---------------------------------------------------------------------------
__global__ __launch_bounds__(256, 4)
void vq_gather_kernel(const float* __restrict__ z, const float* __restrict__ emb,
                      float* __restrict__ out, int writeScalars) {
    __shared__ int   sIdx[BLK_M];
    __shared__ float Ebuf[EBUF_HALF];
    __shared__ float red[8];
    __shared__ int   sLast;

    const int tile = blockIdx.x >> 3;
    const int p    = blockIdx.x & 7;
    const int tid = threadIdx.x;
    const int w = tid >> 5, lane = tid & 31;
    const int n0 = tile * BLK_M;
    const int b  = n0 >> 12;
    const int s0 = n0 & (SPB - 1);
    const float* zb = z + (size_t)b * (CDIM * SPB) + s0;
    float* zqout = out + (size_t)b * (CDIM * SPB) + s0;

    if (tid < BLK_M) sIdx[tid] = gIdx[n0 + tid];
    __syncthreads();

#pragma unroll
    for (int r = 0; r < 16; r++) {
        int m = w * 16 + r;
        Ebuf[lane * EPAD + m] = emb[(size_t)sIdx[m] * CDIM + p * 32 + lane];
    }
    __syncthreads();

    float lsse = 0.f;
#pragma unroll
    for (int j = 0; j < 16; j++) {
        int id = tid + 256 * j;
        int cc = id >> 7, m = id & 127;
        float v  = Ebuf[cc * EPAD + m];
        int c = p * 32 + cc;
        float zv = zb[(size_t)c * SPB + m];
        float diff = __fsub_rn(v, zv);           // z_q - zp, single rounding
        lsse = fmaf(diff, diff, lsse);
        zqout[(size_t)c * SPB + m] = __fadd_rn(zv, diff);  // zp + sg(z_q - zp)
    }
#pragma unroll
    for (int o = 16; o > 0; o >>= 1) lsse += __shfl_xor_sync(0xffffffffu, lsse, o);
    if (lane == 0) red[w] = lsse;
    __syncthreads();
    if (tid == 0) {
        float s = 0.f;
        for (int i = 0; i < 8; i++) s += red[i];
        atomicAdd(&g_sse, s);
    }

    // ---- fused finalize: last-finishing block computes loss + perplexity ----
    if (!writeScalars) return;
    if (tid == 0) {
        __threadfence();
        sLast = (atomicAdd(&g_done, 1) == (int)gridDim.x - 1);
    }
    __syncthreads();
    if (!sLast) return;
    float h = 0.f;
#pragma unroll
    for (int q = 0; q < 4; q++) {
        float c = (float)g_counts[tid + 256 * q];
        float e = c * (1.0f / 32768.0f);
        h += e * logf(e + 1e-10f);
    }
#pragma unroll
    for (int o = 16; o > 0; o >>= 1) h += __shfl_xor_sync(0xffffffffu, h, o);
    if (lane == 0) red[w] = h;
    __syncthreads();
    if (tid == 0) {
        float v = 0.f;
        for (int i = 0; i < 8; i++) v += red[i];
        // LEGACY loss = mse + 0.25*mse = 1.25*mse
        out[ZQ_ELEMS]     = 1.25f * g_sse * (1.0f / 8388608.0f);
        out[ZQ_ELEMS + 1] = expf(-v);
        g_done = 0;                       // reset for deterministic graph replay
    }
}

// ---------------------------------------------------------------------------
extern "C" void kernel_launch(void* const* d_in, const int* in_sizes, int n_in,
                              void* d_out, int out_size) {
    const float* z   = (const float*)d_in[0];
    const float* emb = (const float*)d_in[1];
    if (n_in >= 2 && in_sizes[0] == KCODES * CDIM && in_sizes[1] == ZQ_ELEMS) {
        // defensive: inputs arrived swapped
        z   = (const float*)d_in[1];
        emb = (const float*)d_in[0];
    }
    float* out = (float*)d_out;
    int writeScalars = out_size >= ZQ_ELEMS + 2;
    int writeIdx     = out_size >= ZQ_ELEMS + 2 + NROWS;

    size_t smem = SMEM_FLOATS * sizeof(float);   // 165376 B
    cudaFuncSetAttribute(vq_gemm_kernel,
                         cudaFuncAttributeMaxDynamicSharedMemorySize, (int)smem);

    bias_kernel<<<64, 256>>>(emb);
    prep_a_kernel<<<128, 256>>>(z);
    vq_gemm_kernel<<<GRID_A, 256, smem>>>(z, emb);
    vq_merge_kernel<<<NROWS / BLK_M, BLK_M>>>(out, writeIdx);
    vq_gather_kernel<<<GRID_G, 256>>>(z, emb, out, writeScalars);
}